// round 6
// baseline (speedup 1.0000x reference)
#include <cuda_runtime.h>
#include <stdint.h>

// SpikeFP64Divider: gate-level FP64 restoring divider on rows of 64 {0,1} floats.
// Integer replica of the exact circuit semantics (13-bit modular exponent math,
// subnormal inputs treated as normals, mantissa-round carry-out structurally 0).
//
// R5: fully vectorized transpose. LDG.128 loads (4x fewer LSU ops, 4x bytes in
// flight), 4 ballots per vector, owner-lane raw-ballot capture, one-time
// spread4+brev64 row assembly, STG.128 stores via hi/lo shuffle broadcast.

static __device__ __forceinline__ uint64_t spread4(uint32_t h16) {
    // 16-bit input, bit m -> bit 4m of a 64-bit word
    uint64_t x = h16;
    x = (x | (x << 24)) & 0x000000FF000000FFull;
    x = (x | (x << 12)) & 0x000F000F000F000Full;
    x = (x | (x << 6))  & 0x0303030303030303ull;
    x = (x | (x << 3))  & 0x1111111111111111ull;
    return x;
}

__global__ __launch_bounds__(256, 3) void spike_div_kernel(
    const float* __restrict__ A, const float* __restrict__ B, float* __restrict__ O)
{
    const unsigned FULL = 0xFFFFFFFFu;
    const int lane = threadIdx.x & 31;
    const int warp = threadIdx.x >> 5;

    // Each warp owns 32 consecutive rows = 2048 floats = 512 uint4.
    // uint4 index i = k*32 + lane  ->  row 2k + (lane>>4), cols 4*(lane&15)..+3
    const long long elemBase = (((long long)blockIdx.x * 8 + warp) * 32) * 64;
    const uint4* __restrict__ Au = reinterpret_cast<const uint4*>(A + elemBase);
    const uint4* __restrict__ Bu = reinterpret_cast<const uint4*>(B + elemBase);

    // ---- Pack: ballot per component, owner lane (row index) captures ----
    uint32_t capA[4] = {0u, 0u, 0u, 0u};
    uint32_t capB[4] = {0u, 0u, 0u, 0u};
    const int myk = lane >> 1;            // the load index whose ballots I own

#pragma unroll
    for (int k0 = 0; k0 < 16; k0 += 4) {
        uint4 xa[4], xb[4];
#pragma unroll
        for (int j = 0; j < 4; j++) xa[j] = Au[(k0 + j) * 32 + lane];
#pragma unroll
        for (int j = 0; j < 4; j++) xb[j] = Bu[(k0 + j) * 32 + lane];
#pragma unroll
        for (int j = 0; j < 4; j++) {
            const int k = k0 + j;
            const uint32_t a0 = __ballot_sync(FULL, xa[j].x != 0u);
            const uint32_t a1 = __ballot_sync(FULL, xa[j].y != 0u);
            const uint32_t a2 = __ballot_sync(FULL, xa[j].z != 0u);
            const uint32_t a3 = __ballot_sync(FULL, xa[j].w != 0u);
            if (myk == k) { capA[0] = a0; capA[1] = a1; capA[2] = a2; capA[3] = a3; }
            const uint32_t b0 = __ballot_sync(FULL, xb[j].x != 0u);
            const uint32_t b1 = __ballot_sync(FULL, xb[j].y != 0u);
            const uint32_t b2 = __ballot_sync(FULL, xb[j].z != 0u);
            const uint32_t b3 = __ballot_sync(FULL, xb[j].w != 0u);
            if (myk == k) { capB[0] = b0; capB[1] = b1; capB[2] = b2; capB[3] = b3; }
        }
    }

    // Assemble row words: lane r owns row r. Ballot bit m (within my half) is
    // col 4m+j; spread4 -> bit 4m, brev64 -> bit 63-4m, >>j -> bit 63-(4m+j).
    uint64_t wa = 0ull, wb = 0ull;
    const bool hiHalf = (lane & 1) != 0;
#pragma unroll
    for (int j = 0; j < 4; j++) {
        const uint32_t ha = hiHalf ? (capA[j] >> 16) : (capA[j] & 0xFFFFu);
        wa |= (__brevll(spread4(ha)) >> j);
        const uint32_t hb = hiHalf ? (capB[j] >> 16) : (capB[j] & 0xFFFFu);
        wb |= (__brevll(spread4(hb)) >> j);
    }

    // ---- Circuit replica (one row per lane) ----
    const uint64_t M52 = 0x000FFFFFFFFFFFFFull;
    const uint32_t s_out = (uint32_t)((wa ^ wb) >> 63);
    const uint32_t ea = (uint32_t)(wa >> 52) & 0x7FFu;
    const uint32_t eb = (uint32_t)(wb >> 52) & 0x7FFu;
    const uint64_t ma = wa & M52;
    const uint64_t mb = wb & M52;

    const bool a_zero = (ea == 0u)     && (ma == 0ull);
    const bool b_zero = (eb == 0u)     && (mb == 0ull);
    const bool a_inf  = (ea == 0x7FFu) && (ma == 0ull);
    const bool b_inf  = (eb == 0x7FFu) && (mb == 0ull);
    const bool a_nan  = (ea == 0x7FFu) && (ma != 0ull);
    const bool b_nan  = (eb == 0x7FFu) && (mb != 0ull);

    const bool r_nan  = a_nan || b_nan || (a_zero && b_zero) || (a_inf && b_inf);
    const bool r_inf  = (!a_zero && b_zero) || (a_inf && !b_inf);
    const bool r_zero = (a_zero && !b_zero) || (!a_inf && b_inf);

    // 13-bit modular exponent arithmetic, as the ripple circuits do.
    int exp13 = ((int)ea - (int)eb + 1023) & 8191;

    // ---- Exact Q = floor(a * 2^56 / d) via 2 base-2^28 digits ----
    const uint64_t a = (1ull << 53) | (ma << 1);
    const uint64_t d = (1ull << 53) | (mb << 1);
    const int64_t  ds = (int64_t)d;
    const double inv = 1.0 / (double)d;

    int64_t q1 = (int64_t)((double)a * 0x1p28 * inv);
    int64_t r1 = (int64_t)((a << 28) - (uint64_t)q1 * d);
    if (r1 < 0)   { q1--; r1 += ds; }
    if (r1 < 0)   { q1--; r1 += ds; }
    if (r1 >= ds) { q1++; r1 -= ds; }

    int64_t q2 = (int64_t)((double)r1 * 0x1p28 * inv);
    int64_t r2 = (int64_t)(((uint64_t)r1 << 28) - (uint64_t)q2 * d);
    if (r2 < 0)   { q2--; r2 += ds; }
    if (r2 < 0)   { q2--; r2 += ds; }
    if (r2 >= ds) { q2++; r2 -= ds; }

    const uint64_t Q = ((uint64_t)q1 << 28) + (uint64_t)q2;  // 57-bit quotient
    const bool remnz = (r2 != 0);

    // Normalize + guard/round/sticky (Q bit 56 = first quotient bit).
    const uint32_t q0 = (uint32_t)(Q >> 56) & 1u;
    uint64_t mant;
    uint32_t rnd;
    bool sticky;
    if (q0) {
        mant   = (Q >> 4) & M52;
        rnd    = (uint32_t)(Q >> 3) & 1u;
        sticky = ((Q & 7ull) != 0ull) || remnz;
    } else {
        mant   = (Q >> 3) & M52;
        rnd    = (uint32_t)(Q >> 2) & 1u;
        sticky = ((Q & 3ull) != 0ull) || remnz;
        exp13  = (exp13 - 1) & 8191;
    }

    // RNE; circuit's 53-bit incrementer carry-out is structurally 0:
    // mantissa overflow wraps to 0 WITHOUT exponent bump (mask only).
    const uint32_t lsb = (uint32_t)mant & 1u;
    const uint32_t rup = (rnd && (sticky || lsb)) ? 1u : 0u;
    mant = (mant + (uint64_t)rup) & M52;

    const uint32_t exp_field = (uint32_t)exp13 & 0x7FFu;
    const bool ovf = ((exp13 >> 11) & 3) != 0;
    const bool unf = (((exp13 >> 12) & 1) != 0) || (exp13 == 0);

    const uint64_t sbit = (uint64_t)s_out << 63;
    uint64_t out;
    if (r_nan)       out = sbit | (0x7FFull << 52) | (1ull << 51);
    else if (r_inf)  out = sbit | (0x7FFull << 52);
    else if (r_zero) out = sbit;
    else if (ovf)    out = sbit | (0x7FFull << 52);
    else if (unf)    out = sbit;
    else             out = sbit | ((uint64_t)exp_field << 52) | mant;

    // ---- Unpack: shuffle hi/lo from owner lane, STG.128 float4 ----
    const uint32_t hi_o = (uint32_t)(out >> 32);   // cols  0..31 (col c at bit 31-c)
    const uint32_t lo_o = (uint32_t)out;           // cols 32..63
    float4* __restrict__ O4 = reinterpret_cast<float4*>(O + elemBase);
    const int hsel = (lane >> 4) & 1;              // which of the row pair I store
    const bool use_lo = (lane & 8) != 0;           // my 4 cols live in lo word?
    const int nsh = 28 - 4 * (lane & 7);           // nibble shift within word
#pragma unroll
    for (int k = 0; k < 16; k++) {
        const int src = 2 * k + hsel;
        const uint32_t wh = __shfl_sync(FULL, hi_o, src);
        const uint32_t wl = __shfl_sync(FULL, lo_o, src);
        const uint32_t word = use_lo ? wl : wh;
        const uint32_t nib = (word >> nsh) & 0xFu;
        float4 v;
        v.x = __uint_as_float((nib & 8u) ? 0x3F800000u : 0u);
        v.y = __uint_as_float((nib & 4u) ? 0x3F800000u : 0u);
        v.z = __uint_as_float((nib & 2u) ? 0x3F800000u : 0u);
        v.w = __uint_as_float((nib & 1u) ? 0x3F800000u : 0u);
        O4[k * 32 + lane] = v;
    }
}

extern "C" void kernel_launch(void* const* d_in, const int* in_sizes, int n_in,
                              void* d_out, int out_size) {
    const float* A = (const float*)d_in[0];
    const float* B = (const float*)d_in[1];
    float* O = (float*)d_out;
    const int rows = in_sizes[0] / 64;       // 131072
    const int grid = rows / 256;             // 512 blocks, 8 warps x 32 rows
    spike_div_kernel<<<grid, 256>>>(A, B, O);
}